// round 15
// baseline (speedup 1.0000x reference)
#include <cuda_runtime.h>
#include <cuda_bf16.h>
#include <cuda_fp16.h>
#include <math.h>
#include <stdint.h>

// Problem constants
#define FRAMES  256
#define PATCHES 64
#define DIM     512
#define HEADS   8
#define DH      64
#define DFF     1024
#define KL      128
#define TT      257
#define TS      65
#define RT      (PATCHES * TT)   // 16448
#define RS      (FRAMES * TS)    // 16640

#define FLAG_BIAS 1
#define FLAG_RES  2
#define FLAG_GELU 4

// -------------------- scratch --------------------------------------------
__device__ float g_yt  [RT * DIM];
__device__ float g_ys2 [RS * DIM];
// fp16 activations
__device__ __align__(16) __half g_xth  [RT * DIM];
__device__ __align__(16) __half g_ysh  [RS * DIM];
__device__ __align__(16) __half g_qkvh [RS * 3 * DIM];
__device__ __align__(16) __half g_attnh[RS * DIM];
__device__ __align__(16) __half g_ys2h [RS * DIM];
__device__ __align__(16) __half g_hh   [RS * DFF];
__device__ __align__(16) __half g_kprojh[FRAMES * KL * DIM];
__device__ __align__(16) __half g_vprojh[FRAMES * KL * DIM];
// fp16 weights
__device__ __align__(16) __half g_hWqkv_t[DIM * 3 * DIM];
__device__ __align__(16) __half g_hWo_t  [DIM * DIM];
__device__ __align__(16) __half g_hWqkv_s[DIM * 3 * DIM];
__device__ __align__(16) __half g_hWo_s  [DIM * DIM];
__device__ __align__(16) __half g_hW1    [DIM * DFF];
__device__ __align__(16) __half g_hW2    [DFF * DIM];

// -------------------- helpers --------------------------------------------
__device__ __forceinline__ void mma_f16(float (&c)[4], const uint32_t (&a)[4],
                                        uint32_t b0, uint32_t b1) {
    asm volatile(
        "mma.sync.aligned.m16n8k16.row.col.f32.f16.f16.f32 "
        "{%0,%1,%2,%3}, {%4,%5,%6,%7}, {%8,%9}, {%0,%1,%2,%3};"
        : "+f"(c[0]), "+f"(c[1]), "+f"(c[2]), "+f"(c[3])
        : "r"(a[0]), "r"(a[1]), "r"(a[2]), "r"(a[3]), "r"(b0), "r"(b1));
}

__device__ __forceinline__ void ldsm4(uint32_t (&r)[4], uint32_t addr) {
    asm volatile("ldmatrix.sync.aligned.m8n8.x4.shared.b16 {%0,%1,%2,%3}, [%4];"
        : "=r"(r[0]), "=r"(r[1]), "=r"(r[2]), "=r"(r[3]) : "r"(addr));
}
__device__ __forceinline__ void ldsm4t(uint32_t (&r)[4], uint32_t addr) {
    asm volatile("ldmatrix.sync.aligned.m8n8.x4.trans.shared.b16 {%0,%1,%2,%3}, [%4];"
        : "=r"(r[0]), "=r"(r[1]), "=r"(r[2]), "=r"(r[3]) : "r"(addr));
}

__device__ __forceinline__ uint32_t h2u(__half2 h) { return *(uint32_t*)&h; }

#define CPA16(dst, src) \
    asm volatile("cp.async.cg.shared.global [%0], [%1], 16;" :: "r"(dst), "l"(src))
#define CP_COMMIT() asm volatile("cp.async.commit_group;")
#define CP_WAIT(n)  asm volatile("cp.async.wait_group %0;" :: "n"(n))

// row permutation maps (verified in R14)
__device__ __forceinline__ int map_row(int row, int mode) {
    if (mode == 1) {               // temporal residual: row -> x row
        int p = row / TT, t = row % TT;
        return (t == 0) ? 0 : 1 + (t - 1) * PATCHES + p;
    }
    if (mode == 2) {               // spatial residual: row -> yt row
        int f = row / TS, t = row % TS;
        return (t == 0) ? ((f & 63) * TT) : ((t - 1) * TT + 1 + f);
    }
    return row;
}

// -------------------- fused fp32 -> fp16 weight convert -------------------
#define NQW (DIM * 3 * DIM)
#define NOW (DIM * DIM)
#define NW1 (DIM * DFF)
#define NW2 (DFF * DIM)
#define NCVT (2 * NQW + 2 * NOW + NW1 + NW2)

__global__ void cvt_all(
    const float* __restrict__ w0, __half* __restrict__ h0,
    const float* __restrict__ w1, __half* __restrict__ h1,
    const float* __restrict__ w2, __half* __restrict__ h2,
    const float* __restrict__ w3, __half* __restrict__ h3,
    const float* __restrict__ w4, __half* __restrict__ h4,
    const float* __restrict__ w5, __half* __restrict__ h5)
{
    long i = ((long)blockIdx.x * 256 + threadIdx.x) * 8;
    if (i >= NCVT) return;
    const float* s; __half* d;
    if      (i < NQW)          { s = w0; d = h0; }
    else if ((i -= NQW) < NOW) { s = w1; d = h1; }
    else if ((i -= NOW) < NQW) { s = w2; d = h2; }
    else if ((i -= NQW) < NOW) { s = w3; d = h3; }
    else if ((i -= NOW) < NW1) { s = w4; d = h4; }
    else    { i -= NW1;          s = w5; d = h5; }
    float4 a = *(const float4*)(s + i), b = *(const float4*)(s + i + 4);
    uint4 u = make_uint4(
        h2u(__floats2half2_rn(a.x, a.y)), h2u(__floats2half2_rn(a.z, a.w)),
        h2u(__floats2half2_rn(b.x, b.y)), h2u(__floats2half2_rn(b.z, b.w)));
    *(uint4*)(d + i) = u;
}

// -------------------- fp16 GEMM: 64-K stages (verified R14) ---------------
#define HAS 72
#define HBS 136
#define ASZ (64 * HAS)
#define BSZ (64 * HBS)
#define STAGES 3
#define KSTEP 64
#define GSM ((ASZ + BSZ) * STAGES * 2)   // 79872 bytes

__global__ __launch_bounds__(256) void gemm_h(
    const __half* __restrict__ A, const __half* __restrict__ B,
    const float* __restrict__ bias, const float* __restrict__ R,
    float* __restrict__ C, __half* __restrict__ Ch,
    int M, int N, int K, int flags, int rmode)
{
    extern __shared__ __align__(16) __half sh[];
    __half* As = sh;
    __half* Bs = sh + STAGES * ASZ;

    int tid = threadIdx.x;
    int warp = tid >> 5, lane = tid & 31;
    int wr = warp & 1;
    int wc = warp >> 1;
    int r0 = blockIdx.y * 64;
    int c0 = blockIdx.x * 128;
    int g = lane >> 2, tg = lane & 3;

    float acc[2][4][4];
    #pragma unroll
    for (int mt = 0; mt < 2; mt++)
        #pragma unroll
        for (int nt = 0; nt < 4; nt++)
            #pragma unroll
            for (int i = 0; i < 4; i++) acc[mt][nt][i] = 0.0f;

    int ar = tid >> 2, ac = (tid & 3) * 16;
    const __half* aSrc = A + (size_t)(r0 + ar) * K + ac;
    int br_ = tid >> 2, bc_ = (tid & 3) * 32;
    const __half* bSrc = B + (size_t)br_ * N + c0 + bc_;
    uint32_t aDst = (uint32_t)__cvta_generic_to_shared(&As[ar * HAS + ac]);
    uint32_t bDst = (uint32_t)__cvta_generic_to_shared(&Bs[br_ * HBS + bc_]);

    #pragma unroll
    for (int s = 0; s < STAGES - 1; s++) {
        int k0 = s * KSTEP;
        CPA16(aDst + s * (ASZ * 2),      aSrc + k0);
        CPA16(aDst + s * (ASZ * 2) + 16, aSrc + k0 + 8);
        const __half* bs = bSrc + (size_t)k0 * N;
        #pragma unroll
        for (int j = 0; j < 4; j++)
            CPA16(bDst + s * (BSZ * 2) + j * 16, bs + j * 8);
        CP_COMMIT();
    }

    int l15 = lane & 15, lhi = lane >> 4;
    uint32_t aAddr = (uint32_t)__cvta_generic_to_shared(As)
                   + (uint32_t)(((wr * 32 + l15) * HAS + lhi * 8) * 2);
    int bq = (lane & 7) + ((lane >> 3) & 1) * 8;
    uint32_t bAddr = (uint32_t)__cvta_generic_to_shared(Bs)
                   + (uint32_t)((bq * HBS + wc * 32 + lhi * 8) * 2);

    int buf = 0;
    for (int k0 = 0; k0 < K; k0 += KSTEP) {
        CP_WAIT(STAGES - 2);
        __syncthreads();

        int kn = k0 + (STAGES - 1) * KSTEP;
        if (kn < K) {
            int s = buf + (STAGES - 1); if (s >= STAGES) s -= STAGES;
            CPA16(aDst + s * (ASZ * 2),      aSrc + kn);
            CPA16(aDst + s * (ASZ * 2) + 16, aSrc + kn + 8);
            const __half* bs = bSrc + (size_t)kn * N;
            #pragma unroll
            for (int j = 0; j < 4; j++)
                CPA16(bDst + s * (BSZ * 2) + j * 16, bs + j * 8);
        }
        CP_COMMIT();

        uint32_t aB = aAddr + buf * (ASZ * 2);
        uint32_t bB = bAddr + buf * (BSZ * 2);
        #pragma unroll
        for (int kk = 0; kk < KSTEP; kk += 16) {
            uint32_t a[2][4], b[2][4];
            ldsm4 (a[0], aB + kk * 2);
            ldsm4 (a[1], aB + kk * 2 + 16 * HAS * 2);
            ldsm4t(b[0], bB + kk * HBS * 2);
            ldsm4t(b[1], bB + kk * HBS * 2 + 16 * 2);
            #pragma unroll
            for (int mt = 0; mt < 2; mt++)
                #pragma unroll
                for (int nt = 0; nt < 4; nt++)
                    mma_f16(acc[mt][nt], a[mt],
                            b[nt >> 1][(nt & 1) * 2], b[nt >> 1][(nt & 1) * 2 + 1]);
        }
        buf++; if (buf == STAGES) buf = 0;
    }

    #pragma unroll
    for (int mt = 0; mt < 2; mt++) {
        #pragma unroll
        for (int nt = 0; nt < 4; nt++) {
            int col = c0 + wc * 32 + nt * 8 + 2 * tg;
            #pragma unroll
            for (int half = 0; half < 2; half++) {
                int row = r0 + wr * 32 + mt * 16 + g + half * 8;
                float v0 = acc[mt][nt][half * 2 + 0];
                float v1 = acc[mt][nt][half * 2 + 1];
                if (flags & FLAG_BIAS) { v0 += bias[col]; v1 += bias[col + 1]; }
                if (flags & FLAG_GELU) {
                    v0 = 0.5f * v0 * (1.0f + erff(v0 * 0.70710678118654752f));
                    v1 = 0.5f * v1 * (1.0f + erff(v1 * 0.70710678118654752f));
                }
                if (flags & FLAG_RES) {
                    int rrow = map_row(row, rmode);
                    float2 rr = *(const float2*)&R[(size_t)rrow * N + col];
                    v0 += rr.x; v1 += rr.y;
                }
                if (C)
                    *(float2*)&C[(size_t)row * N + col] = make_float2(v0, v1);
                if (Ch)
                    *(__half2*)&Ch[(size_t)row * N + col] = __floats2half2_rn(v0, v1);
            }
        }
    }
}

// -------------------- fp16 tensor-core attention (verified R13) -----------
#define KVSTR 72
#define KVSZ  (64 * KVSTR)

__global__ __launch_bounds__(256) void attn_h(
    const __half* __restrict__ Q, int qStride,
    const __half* __restrict__ Kp, const __half* __restrict__ Vp, int kvStride,
    __half* __restrict__ O, int Tq, int Tk, int ktiles, float scale)
{
    extern __shared__ __align__(16) char smh[];
    const int SSTh = ktiles * 64 + 8;
    __half* Ssm = (__half*)smh;
    __half* KV  = (__half*)(smh + (size_t)64 * SSTh * 2);
    float*  srow = (float*)(smh + (size_t)64 * SSTh * 2 + 2 * KVSZ * 2);

    int qt = blockIdx.x, b = blockIdx.y, h = blockIdx.z;
    int tid = threadIdx.x, warp = tid >> 5, lane = tid & 31;
    int g = lane >> 2, tg = lane & 3;
    int wm = warp >> 1, wn = warp & 1;
    int rb = wm * 16;
    int q0 = qt * 64;
    int l15 = lane & 15, lhi = lane >> 4;
    int bq = (lane & 7) + ((lane >> 3) & 1) * 8;

    const __half* Qb = Q  + (size_t)b * Tq * qStride  + h * DH;
    const __half* Kb = Kp + (size_t)b * Tk * kvStride + h * DH;
    const __half* Vb = Vp + (size_t)b * Tk * kvStride + h * DH;

    uint32_t kvBase = (uint32_t)__cvta_generic_to_shared(KV);
    uint32_t sBase  = (uint32_t)__cvta_generic_to_shared(Ssm);

    int lr = tid >> 2, lc = (tid & 3) * 16;

    {
        int rq = q0 + lr; if (rq > Tq - 1) rq = Tq - 1;
        const __half* src = Qb + (size_t)rq * qStride + lc;
        *(uint4*)&KV[lr * KVSTR + lc]     = *(const uint4*)src;
        *(uint4*)&KV[lr * KVSTR + lc + 8] = *(const uint4*)(src + 8);
    }
    __syncthreads();

    uint32_t aq[4][4];
    {
        uint32_t qA = kvBase + (uint32_t)(((rb + l15) * KVSTR + lhi * 8) * 2);
        #pragma unroll
        for (int kk = 0; kk < 4; kk++) ldsm4(aq[kk], qA + kk * 32);
    }
    __syncthreads();

    auto prefK = [&](int bf, int kt) {
        int rk = kt * 64 + lr; if (rk > Tk - 1) rk = Tk - 1;
        const __half* src = Kb + (size_t)rk * kvStride + lc;
        uint32_t dst = kvBase + (uint32_t)((bf * KVSZ + lr * KVSTR + lc) * 2);
        CPA16(dst, src);
        CPA16(dst + 16, src + 8);
        CP_COMMIT();
    };
    auto prefV = [&](int bf, int kt) {
        int rk = kt * 64 + lr; if (rk > Tk - 1) rk = Tk - 1;
        const __half* src = Vb + (size_t)rk * kvStride + lc;
        uint32_t dst = kvBase + (uint32_t)((bf * KVSZ + lr * KVSTR + lc) * 2);
        CPA16(dst, src);
        CPA16(dst + 16, src + 8);
        CP_COMMIT();
    };

    prefK(0, 0);
    for (int kt = 0; kt < ktiles; kt++) {
        if (kt + 1 < ktiles) { prefK((kt + 1) & 1, kt + 1); CP_WAIT(1); }
        else                 { CP_WAIT(0); }
        __syncthreads();

        float cS[4][4];
        #pragma unroll
        for (int nt = 0; nt < 4; nt++)
            #pragma unroll
            for (int i = 0; i < 4; i++) cS[nt][i] = 0.0f;

        uint32_t kB = kvBase + (uint32_t)(((kt & 1) * KVSZ
                     + (wn * 32 + l15) * KVSTR + lhi * 8) * 2);
        #pragma unroll
        for (int kk = 0; kk < 4; kk++) {
            uint32_t kb0[4], kb1[4];
            ldsm4(kb0, kB + kk * 32);
            ldsm4(kb1, kB + 16 * KVSTR * 2 + kk * 32);
            mma_f16(cS[0], aq[kk], kb0[0], kb0[2]);
            mma_f16(cS[1], aq[kk], kb0[1], kb0[3]);
            mma_f16(cS[2], aq[kk], kb1[0], kb1[2]);
            mma_f16(cS[3], aq[kk], kb1[1], kb1[3]);
        }

        #pragma unroll
        for (int nt = 0; nt < 4; nt++) {
            int cl = wn * 32 + nt * 8 + 2 * tg;
            int cg = kt * 64 + cl;
            float s0 = (cg     < Tk) ? cS[nt][0] * scale : -60000.0f;
            float s1 = (cg + 1 < Tk) ? cS[nt][1] * scale : -60000.0f;
            float s2 = (cg     < Tk) ? cS[nt][2] * scale : -60000.0f;
            float s3 = (cg + 1 < Tk) ? cS[nt][3] * scale : -60000.0f;
            *(__half2*)&Ssm[(rb + g) * SSTh + kt * 64 + cl]     = __floats2half2_rn(s0, s1);
            *(__half2*)&Ssm[(rb + g + 8) * SSTh + kt * 64 + cl] = __floats2half2_rn(s2, s3);
        }
        __syncthreads();
    }

    prefV(0, 0);

    {
        int row = tid >> 2, sub = tid & 3;
        __half2* Sr = (__half2*)&Ssm[row * SSTh];
        int nc2 = ktiles * 32;
        float m = -1e30f;
        for (int c = sub; c < nc2; c += 4) {
            float2 v = __half22float2(Sr[c]);
            m = fmaxf(m, fmaxf(v.x, v.y));
        }
        m = fmaxf(m, __shfl_xor_sync(0xffffffffu, m, 1));
        m = fmaxf(m, __shfl_xor_sync(0xffffffffu, m, 2));
        float s = 0.0f;
        for (int c = sub; c < nc2; c += 4) {
            float2 v = __half22float2(Sr[c]);
            float e0 = __expf(v.x - m), e1 = __expf(v.y - m);
            s += e0 + e1;
            Sr[c] = __floats2half2_rn(e0, e1);
        }
        s += __shfl_xor_sync(0xffffffffu, s, 1);
        s += __shfl_xor_sync(0xffffffffu, s, 2);
        if (sub == 0) srow[row] = 1.0f / s;
    }
    __syncthreads();

    float cO[4][4];
    #pragma unroll
    for (int nt = 0; nt < 4; nt++)
        #pragma unroll
        for (int i = 0; i < 4; i++) cO[nt][i] = 0.0f;

    uint32_t pA = sBase + (uint32_t)(((rb + l15) * SSTh + lhi * 8) * 2);
    for (int kt = 0; kt < ktiles; kt++) {
        if (kt + 1 < ktiles) { prefV((kt + 1) & 1, kt + 1); CP_WAIT(1); }
        else                 { CP_WAIT(0); }
        __syncthreads();

        uint32_t vB = kvBase + (uint32_t)(((kt & 1) * KVSZ
                     + bq * KVSTR + wn * 32 + lhi * 8) * 2);
        #pragma unroll
        for (int kk = 0; kk < 4; kk++) {
            uint32_t ap[4];
            ldsm4(ap, pA + (kt * 64 + kk * 16) * 2);
            uint32_t vb0[4], vb1[4];
            ldsm4t(vb0, vB + kk * 16 * KVSTR * 2);
            ldsm4t(vb1, vB + kk * 16 * KVSTR * 2 + 32);
            mma_f16(cO[0], ap, vb0[0], vb0[1]);
            mma_f16(cO[1], ap, vb0[2], vb0[3]);
            mma_f16(cO[2], ap, vb1[0], vb1[1]);
            mma_f16(cO[3], ap, vb1[2], vb1[3]);
        }
        __syncthreads();
    }

    float inv0 = srow[rb + g], inv1 = srow[rb + g + 8];
    #pragma unroll
    for (int nt = 0; nt < 4; nt++) {
        int dl = wn * 32 + nt * 8 + 2 * tg;
        int r0g = q0 + rb + g;
        if (r0g < Tq)
            *(__half2*)&O[((size_t)b * Tq + r0g) * DIM + h * DH + dl] =
                __floats2half2_rn(cO[nt][0] * inv0, cO[nt][1] * inv0);
        int r1g = q0 + rb + g + 8;
        if (r1g < Tq)
            *(__half2*)&O[((size_t)b * Tq + r1g) * DIM + h * DH + dl] =
                __floats2half2_rn(cO[nt][2] * inv1, cO[nt][3] * inv1);
    }
}

// -------------------- Linformer K/V projection (verified) -----------------
__global__ __launch_bounds__(256) void linproj_h(
    const __half* __restrict__ qkv, const float* __restrict__ E,
    __half* __restrict__ kproj, __half* __restrict__ vproj)
{
    __shared__ float Es[TS * 32];
    __shared__ float Ksm[TS * 64];

    int b = blockIdx.x;
    int c0 = blockIdx.y * 64;
    int zz = blockIdx.z;
    int kvsel = zz & 1;
    int kkt = zz >> 1;
    int tid = threadIdx.x;

    int colbase = DIM + kvsel * DIM + c0;
    for (int i = tid; i < TS * 64; i += 256) {
        int j = i >> 6, c = i & 63;
        Ksm[i] = __half2float(qkv[((size_t)b * TS + j) * (3 * DIM) + colbase + c]);
    }
    for (int i = tid; i < TS * 32; i += 256) {
        int j = i >> 5, q = i & 31;
        Es[i] = E[j * KL + kkt * 32 + q];
    }
    __syncthreads();

    int c = tid & 63, kg = tid >> 6;
    float acc[8];
    #pragma unroll
    for (int i = 0; i < 8; i++) acc[i] = 0.0f;

    for (int j = 0; j < TS; j++) {
        float kv = Ksm[j * 64 + c];
        #pragma unroll
        for (int i = 0; i < 8; i++)
            acc[i] += kv * Es[j * 32 + kg * 8 + i];
    }

    __half* dst = kvsel ? vproj : kproj;
    #pragma unroll
    for (int i = 0; i < 8; i++) {
        int kk = kkt * 32 + kg * 8 + i;
        dst[((size_t)b * KL + kk) * DIM + c0 + c] = __float2half_rn(acc[i]);
    }
}

// -------------------- token rearrangement (fp16-only outputs) -------------
__global__ void gather_t_kernel(const float* __restrict__ x,
                                __half* __restrict__ xth)
{
    int row = blockIdx.x;
    int p = row / TT, t = row % TT;
    const float4* s = (const float4*)(t == 0 ? x
                        : x + (size_t)(1 + (t - 1) * PATCHES + p) * DIM);
    float4 v = s[threadIdx.x];
    uint2 h = make_uint2(h2u(__floats2half2_rn(v.x, v.y)),
                         h2u(__floats2half2_rn(v.z, v.w)));
    *(uint2*)(xth + (size_t)row * DIM + threadIdx.x * 4) = h;
}

__global__ void gather_s_kernel(const float* __restrict__ yt,
                                __half* __restrict__ ysh)
{
    int row = blockIdx.x;
    int f = row / TS, t = row % TS;
    const float* src = (t == 0)
        ? yt + (size_t)((f & 63) * TT) * DIM
        : yt + (size_t)((t - 1) * TT + 1 + f) * DIM;
    float4 v = ((const float4*)src)[threadIdx.x];
    uint2 h = make_uint2(h2u(__floats2half2_rn(v.x, v.y)),
                         h2u(__floats2half2_rn(v.z, v.w)));
    *(uint2*)(ysh + (size_t)row * DIM + threadIdx.x * 4) = h;
}

// -------------------- launch ----------------------------------------------
extern "C" void kernel_launch(void* const* d_in, const int* in_sizes, int n_in,
                              void* d_out, int out_size)
{
    const float* x      = (const float*)d_in[0];
    const float* Wqkv_t = (const float*)d_in[1];
    const float* Wo_t   = (const float*)d_in[2];
    const float* Wqkv_s = (const float*)d_in[3];
    const float* Wo_s   = (const float*)d_in[4];
    const float* E      = (const float*)d_in[5];
    const float* W1     = (const float*)d_in[6];
    const float* b1     = (const float*)d_in[7];
    const float* W2     = (const float*)d_in[8];
    const float* b2     = (const float*)d_in[9];
    float* out = (float*)d_out;

    float *yt, *ys2;
    __half *xth, *ysh, *qkvh, *attnh, *ys2h, *hh, *kprojh, *vprojh;
    __half *hQt, *hOt, *hQs, *hOs, *hW1, *hW2;
    cudaGetSymbolAddress((void**)&yt,     g_yt);
    cudaGetSymbolAddress((void**)&ys2,    g_ys2);
    cudaGetSymbolAddress((void**)&xth,    g_xth);
    cudaGetSymbolAddress((void**)&ysh,    g_ysh);
    cudaGetSymbolAddress((void**)&qkvh,   g_qkvh);
    cudaGetSymbolAddress((void**)&attnh,  g_attnh);
    cudaGetSymbolAddress((void**)&ys2h,   g_ys2h);
    cudaGetSymbolAddress((void**)&hh,     g_hh);
    cudaGetSymbolAddress((void**)&kprojh, g_kprojh);
    cudaGetSymbolAddress((void**)&vprojh, g_vprojh);
    cudaGetSymbolAddress((void**)&hQt,    g_hWqkv_t);
    cudaGetSymbolAddress((void**)&hOt,    g_hWo_t);
    cudaGetSymbolAddress((void**)&hQs,    g_hWqkv_s);
    cudaGetSymbolAddress((void**)&hOs,    g_hWo_s);
    cudaGetSymbolAddress((void**)&hW1,    g_hW1);
    cudaGetSymbolAddress((void**)&hW2,    g_hW2);

    const int ktT = (TT + 63) / 64;          // 5
    const int ktS = (KL + 63) / 64;          // 2
    const int qtT = (TT + 63) / 64;          // 5
    const int qtS = (TS + 63) / 64;          // 2
    const int smemT = 64 * (ktT * 64 + 8) * 2 + 2 * KVSZ * 2 + 64 * 4;
    const int smemS = 64 * (ktS * 64 + 8) * 2 + 2 * KVSZ * 2 + 64 * 4;
    cudaFuncSetAttribute(attn_h, cudaFuncAttributeMaxDynamicSharedMemorySize, smemT);
    cudaFuncSetAttribute(gemm_h, cudaFuncAttributeMaxDynamicSharedMemorySize, GSM);

    // 0) fused weight conversion
    cvt_all<<<(NCVT / 8 + 255) / 256, 256>>>(
        Wqkv_t, hQt, Wo_t, hOt, Wqkv_s, hQs, Wo_s, hOs, W1, hW1, W2, hW2);

    // 1) temporal token gather -> fp16 (contiguous A for QKV)
    gather_t_kernel<<<RT, 128>>>(x, xth);

    // 2) temporal QKV
    gemm_h<<<dim3(3 * DIM / 128, RT / 64), 256, GSM>>>(
        xth, hQt, nullptr, nullptr, nullptr, qkvh, RT, 3 * DIM, DIM, 0, 0);

    // 3) temporal attention
    attn_h<<<dim3(qtT, PATCHES, HEADS), 256, smemT>>>(
        qkvh, 3 * DIM, qkvh + DIM, qkvh + 2 * DIM, 3 * DIM, attnh, TT, TT, ktT, 0.125f);

    // 4) Wo_t + residual (R rows gathered from x via rmode=1) -> yt fp32
    gemm_h<<<dim3(DIM / 128, RT / 64), 256, GSM>>>(
        attnh, hOt, nullptr, x, yt, nullptr, RT, DIM, DIM, FLAG_RES, 1);

    // 5) spatial gather -> fp16
    gather_s_kernel<<<RS, 128>>>(yt, ysh);

    // 6) spatial QKV
    gemm_h<<<dim3(3 * DIM / 128, RS / 64), 256, GSM>>>(
        ysh, hQs, nullptr, nullptr, nullptr, qkvh, RS, 3 * DIM, DIM, 0, 0);

    // 7) Linformer K/V projection
    linproj_h<<<dim3(FRAMES, DIM / 64, 8), 256>>>(qkvh, E, kprojh, vprojh);

    // 8) spatial attention (2 query tiles)
    attn_h<<<dim3(qtS, FRAMES, HEADS), 256, smemS>>>(
        qkvh, 3 * DIM, kprojh, vprojh, DIM, attnh, TS, KL, ktS, 0.125f);

    // 9) Wo_s + residual (R rows gathered from yt via rmode=2) -> ys2 + ys2h
    gemm_h<<<dim3(DIM / 128, RS / 64), 256, GSM>>>(
        attnh, hOs, nullptr, yt, ys2, ys2h, RS, DIM, DIM, FLAG_RES, 2);

    // 10) MLP up + bias + GELU (fp16 output)
    gemm_h<<<dim3(DFF / 128, RS / 64), 256, GSM>>>(
        ys2h, hW1, b1, nullptr, nullptr, hh, RS, DFF, DIM, FLAG_BIAS | FLAG_GELU, 0);

    // 11) MLP down + bias + residual -> final fp32 output
    gemm_h<<<dim3(DIM / 128, RS / 64), 256, GSM>>>(
        hh, hW2, b2, ys2, out, nullptr, RS, DIM, DFF, FLAG_BIAS | FLAG_RES, 0);
}

// round 16
// speedup vs baseline: 1.1667x; 1.1667x over previous
#include <cuda_runtime.h>
#include <cuda_bf16.h>
#include <cuda_fp16.h>
#include <math.h>
#include <stdint.h>

// Problem constants
#define FRAMES  256
#define PATCHES 64
#define DIM     512
#define HEADS   8
#define DH      64
#define DFF     1024
#define KL      128
#define TT      257
#define TS      65
#define RT      (PATCHES * TT)   // 16448
#define RS      (FRAMES * TS)    // 16640

#define FLAG_BIAS 1
#define FLAG_RES  2
#define FLAG_GELU 4

// -------------------- scratch --------------------------------------------
__device__ float g_yt  [RT * DIM];
__device__ float g_ys2 [RS * DIM];
// fp16 activations
__device__ __align__(16) __half g_xth  [RT * DIM];
__device__ __align__(16) __half g_ysh  [RS * DIM];
__device__ __align__(16) __half g_qkvh [RS * 3 * DIM];
__device__ __align__(16) __half g_attnh[RS * DIM];
__device__ __align__(16) __half g_ys2h [RS * DIM];
__device__ __align__(16) __half g_hh   [RS * DFF];
__device__ __align__(16) __half g_kprojh[FRAMES * KL * DIM];
__device__ __align__(16) __half g_vprojh[FRAMES * KL * DIM];
// fp16 weights
__device__ __align__(16) __half g_hWqkv_t[DIM * 3 * DIM];
__device__ __align__(16) __half g_hWo_t  [DIM * DIM];
__device__ __align__(16) __half g_hWqkv_s[DIM * 3 * DIM];
__device__ __align__(16) __half g_hWo_s  [DIM * DIM];
__device__ __align__(16) __half g_hW1    [DIM * DFF];
__device__ __align__(16) __half g_hW2    [DFF * DIM];

// -------------------- helpers --------------------------------------------
__device__ __forceinline__ void mma_f16(float (&c)[4], const uint32_t (&a)[4],
                                        uint32_t b0, uint32_t b1) {
    asm volatile(
        "mma.sync.aligned.m16n8k16.row.col.f32.f16.f16.f32 "
        "{%0,%1,%2,%3}, {%4,%5,%6,%7}, {%8,%9}, {%0,%1,%2,%3};"
        : "+f"(c[0]), "+f"(c[1]), "+f"(c[2]), "+f"(c[3])
        : "r"(a[0]), "r"(a[1]), "r"(a[2]), "r"(a[3]), "r"(b0), "r"(b1));
}

__device__ __forceinline__ void ldsm4(uint32_t (&r)[4], uint32_t addr) {
    asm volatile("ldmatrix.sync.aligned.m8n8.x4.shared.b16 {%0,%1,%2,%3}, [%4];"
        : "=r"(r[0]), "=r"(r[1]), "=r"(r[2]), "=r"(r[3]) : "r"(addr));
}
__device__ __forceinline__ void ldsm4t(uint32_t (&r)[4], uint32_t addr) {
    asm volatile("ldmatrix.sync.aligned.m8n8.x4.trans.shared.b16 {%0,%1,%2,%3}, [%4];"
        : "=r"(r[0]), "=r"(r[1]), "=r"(r[2]), "=r"(r[3]) : "r"(addr));
}

__device__ __forceinline__ uint32_t h2u(__half2 h) { return *(uint32_t*)&h; }

#define CPA16(dst, src) \
    asm volatile("cp.async.cg.shared.global [%0], [%1], 16;" :: "r"(dst), "l"(src))
#define CP_COMMIT() asm volatile("cp.async.commit_group;")
#define CP_WAIT(n)  asm volatile("cp.async.wait_group %0;" :: "n"(n))

// row permutation maps for residual reads (verified R14/R15)
__device__ __forceinline__ int map_row(int row, int mode) {
    if (mode == 1) {               // temporal residual: row -> x row
        int p = row / TT, t = row % TT;
        return (t == 0) ? 0 : 1 + (t - 1) * PATCHES + p;
    }
    if (mode == 2) {               // spatial residual: row -> yt row
        int f = row / TS, t = row % TS;
        return (t == 0) ? ((f & 63) * TT) : ((t - 1) * TT + 1 + f);
    }
    return row;
}

// -------------------- fused fp32 -> fp16 weight convert (verified) --------
#define NQW (DIM * 3 * DIM)
#define NOW (DIM * DIM)
#define NW1 (DIM * DFF)
#define NW2 (DFF * DIM)
#define NCVT (2 * NQW + 2 * NOW + NW1 + NW2)

__global__ void cvt_all(
    const float* __restrict__ w0, __half* __restrict__ h0,
    const float* __restrict__ w1, __half* __restrict__ h1,
    const float* __restrict__ w2, __half* __restrict__ h2,
    const float* __restrict__ w3, __half* __restrict__ h3,
    const float* __restrict__ w4, __half* __restrict__ h4,
    const float* __restrict__ w5, __half* __restrict__ h5)
{
    long i = ((long)blockIdx.x * 256 + threadIdx.x) * 8;
    if (i >= NCVT) return;
    const float* s; __half* d;
    if      (i < NQW)          { s = w0; d = h0; }
    else if ((i -= NQW) < NOW) { s = w1; d = h1; }
    else if ((i -= NOW) < NQW) { s = w2; d = h2; }
    else if ((i -= NQW) < NOW) { s = w3; d = h3; }
    else if ((i -= NOW) < NW1) { s = w4; d = h4; }
    else    { i -= NW1;          s = w5; d = h5; }
    float4 a = *(const float4*)(s + i), b = *(const float4*)(s + i + 4);
    uint4 u = make_uint4(
        h2u(__floats2half2_rn(a.x, a.y)), h2u(__floats2half2_rn(a.z, a.w)),
        h2u(__floats2half2_rn(b.x, b.y)), h2u(__floats2half2_rn(b.z, b.w)));
    *(uint4*)(d + i) = u;
}

// -------------------- shared GEMM epilogue --------------------------------
__device__ __forceinline__ void gemm_epilogue(
    float (&acc)[2][4][4], const float* bias, const float* R,
    float* C, __half* Ch, int N, int flags, int rmode,
    int r0, int c0, int wr, int wc, int g, int tg)
{
    #pragma unroll
    for (int mt = 0; mt < 2; mt++) {
        #pragma unroll
        for (int nt = 0; nt < 4; nt++) {
            int col = c0 + wc * 32 + nt * 8 + 2 * tg;
            #pragma unroll
            for (int half = 0; half < 2; half++) {
                int row = r0 + wr * 32 + mt * 16 + g + half * 8;
                float v0 = acc[mt][nt][half * 2 + 0];
                float v1 = acc[mt][nt][half * 2 + 1];
                if (flags & FLAG_BIAS) { v0 += bias[col]; v1 += bias[col + 1]; }
                if (flags & FLAG_GELU) {
                    v0 = 0.5f * v0 * (1.0f + erff(v0 * 0.70710678118654752f));
                    v1 = 0.5f * v1 * (1.0f + erff(v1 * 0.70710678118654752f));
                }
                if (flags & FLAG_RES) {
                    int rrow = map_row(row, rmode);
                    float2 rr = *(const float2*)&R[(size_t)rrow * N + col];
                    v0 += rr.x; v1 += rr.y;
                }
                if (C)
                    *(float2*)&C[(size_t)row * N + col] = make_float2(v0, v1);
                if (Ch)
                    *(__half2*)&Ch[(size_t)row * N + col] = __floats2half2_rn(v0, v1);
            }
        }
    }
}

// -------------------- gemm32: KSTEP-32, static smem (verified R13) --------
#define H32A 40
#define H32B 136
#define A32SZ (64 * H32A)   // 2560 halves
#define B32SZ (32 * H32B)   // 4352 halves

__global__ __launch_bounds__(256) void gemm32(
    const __half* __restrict__ A, const __half* __restrict__ B,
    const float* __restrict__ bias, const float* __restrict__ R,
    float* __restrict__ C, __half* __restrict__ Ch,
    int M, int N, int K, int flags, int rmode)
{
    __shared__ __align__(16) __half As[3 * A32SZ];
    __shared__ __align__(16) __half Bs[3 * B32SZ];

    int tid = threadIdx.x;
    int warp = tid >> 5, lane = tid & 31;
    int wr = warp & 1, wc = warp >> 1;
    int r0 = blockIdx.y * 64, c0 = blockIdx.x * 128;
    int g = lane >> 2, tg = lane & 3;

    float acc[2][4][4];
    #pragma unroll
    for (int mt = 0; mt < 2; mt++)
        #pragma unroll
        for (int nt = 0; nt < 4; nt++)
            #pragma unroll
            for (int i = 0; i < 4; i++) acc[mt][nt][i] = 0.0f;

    int ar = tid >> 2, ac = (tid & 3) * 8;
    const __half* aSrc = A + (size_t)(r0 + ar) * K + ac;
    int br_ = tid >> 4, bc_ = (tid & 15) * 8;
    const __half* bSrc0 = B + (size_t)br_ * N + c0 + bc_;
    const __half* bSrc1 = B + (size_t)(br_ + 16) * N + c0 + bc_;
    uint32_t aDst  = (uint32_t)__cvta_generic_to_shared(&As[ar * H32A + ac]);
    uint32_t bDst0 = (uint32_t)__cvta_generic_to_shared(&Bs[br_ * H32B + bc_]);
    uint32_t bDst1 = (uint32_t)__cvta_generic_to_shared(&Bs[(br_ + 16) * H32B + bc_]);

    #pragma unroll
    for (int s = 0; s < 2; s++) {
        int k0 = s * 32;
        CPA16(aDst + s * (A32SZ * 2), aSrc + k0);
        CPA16(bDst0 + s * (B32SZ * 2), bSrc0 + (size_t)k0 * N);
        CPA16(bDst1 + s * (B32SZ * 2), bSrc1 + (size_t)k0 * N);
        CP_COMMIT();
    }

    int l15 = lane & 15, lhi = lane >> 4;
    uint32_t aAddr = (uint32_t)__cvta_generic_to_shared(As)
                   + (uint32_t)(((wr * 32 + l15) * H32A + lhi * 8) * 2);
    int bq = (lane & 7) + ((lane >> 3) & 1) * 8;
    uint32_t bAddr = (uint32_t)__cvta_generic_to_shared(Bs)
                   + (uint32_t)((bq * H32B + wc * 32 + lhi * 8) * 2);

    int buf = 0;
    for (int k0 = 0; k0 < K; k0 += 32) {
        CP_WAIT(1);
        __syncthreads();

        int kn = k0 + 2 * 32;
        if (kn < K) {
            int s = buf + 2; if (s >= 3) s -= 3;
            CPA16(aDst + s * (A32SZ * 2), aSrc + kn);
            CPA16(bDst0 + s * (B32SZ * 2), bSrc0 + (size_t)kn * N);
            CPA16(bDst1 + s * (B32SZ * 2), bSrc1 + (size_t)kn * N);
        }
        CP_COMMIT();

        uint32_t aB = aAddr + buf * (A32SZ * 2);
        uint32_t bB = bAddr + buf * (B32SZ * 2);
        #pragma unroll
        for (int kk = 0; kk < 32; kk += 16) {
            uint32_t a[2][4], b[2][4];
            ldsm4 (a[0], aB + kk * 2);
            ldsm4 (a[1], aB + kk * 2 + 16 * H32A * 2);
            ldsm4t(b[0], bB + kk * H32B * 2);
            ldsm4t(b[1], bB + kk * H32B * 2 + 16 * 2);
            #pragma unroll
            for (int mt = 0; mt < 2; mt++)
                #pragma unroll
                for (int nt = 0; nt < 4; nt++)
                    mma_f16(acc[mt][nt], a[mt],
                            b[nt >> 1][(nt & 1) * 2], b[nt >> 1][(nt & 1) * 2 + 1]);
        }
        buf++; if (buf == 3) buf = 0;
    }

    gemm_epilogue(acc, bias, R, C, Ch, N, flags, rmode, r0, c0, wr, wc, g, tg);
}

// -------------------- gemm64: KSTEP-64, dynamic smem (verified R14) -------
#define H64A 72
#define H64B 136
#define A64SZ (64 * H64A)
#define B64SZ (64 * H64B)
#define GSM ((A64SZ + B64SZ) * 3 * 2)   // 79872 bytes

__global__ __launch_bounds__(256) void gemm64(
    const __half* __restrict__ A, const __half* __restrict__ B,
    const float* __restrict__ bias, const float* __restrict__ R,
    float* __restrict__ C, __half* __restrict__ Ch,
    int M, int N, int K, int flags, int rmode)
{
    extern __shared__ __align__(16) __half sh[];
    __half* As = sh;
    __half* Bs = sh + 3 * A64SZ;

    int tid = threadIdx.x;
    int warp = tid >> 5, lane = tid & 31;
    int wr = warp & 1, wc = warp >> 1;
    int r0 = blockIdx.y * 64, c0 = blockIdx.x * 128;
    int g = lane >> 2, tg = lane & 3;

    float acc[2][4][4];
    #pragma unroll
    for (int mt = 0; mt < 2; mt++)
        #pragma unroll
        for (int nt = 0; nt < 4; nt++)
            #pragma unroll
            for (int i = 0; i < 4; i++) acc[mt][nt][i] = 0.0f;

    int ar = tid >> 2, ac = (tid & 3) * 16;
    const __half* aSrc = A + (size_t)(r0 + ar) * K + ac;
    int br_ = tid >> 2, bc_ = (tid & 3) * 32;
    const __half* bSrc = B + (size_t)br_ * N + c0 + bc_;
    uint32_t aDst = (uint32_t)__cvta_generic_to_shared(&As[ar * H64A + ac]);
    uint32_t bDst = (uint32_t)__cvta_generic_to_shared(&Bs[br_ * H64B + bc_]);

    #pragma unroll
    for (int s = 0; s < 2; s++) {
        int k0 = s * 64;
        CPA16(aDst + s * (A64SZ * 2),      aSrc + k0);
        CPA16(aDst + s * (A64SZ * 2) + 16, aSrc + k0 + 8);
        const __half* bs = bSrc + (size_t)k0 * N;
        #pragma unroll
        for (int j = 0; j < 4; j++)
            CPA16(bDst + s * (B64SZ * 2) + j * 16, bs + j * 8);
        CP_COMMIT();
    }

    int l15 = lane & 15, lhi = lane >> 4;
    uint32_t aAddr = (uint32_t)__cvta_generic_to_shared(As)
                   + (uint32_t)(((wr * 32 + l15) * H64A + lhi * 8) * 2);
    int bq = (lane & 7) + ((lane >> 3) & 1) * 8;
    uint32_t bAddr = (uint32_t)__cvta_generic_to_shared(Bs)
                   + (uint32_t)((bq * H64B + wc * 32 + lhi * 8) * 2);

    int buf = 0;
    for (int k0 = 0; k0 < K; k0 += 64) {
        CP_WAIT(1);
        __syncthreads();

        int kn = k0 + 2 * 64;
        if (kn < K) {
            int s = buf + 2; if (s >= 3) s -= 3;
            CPA16(aDst + s * (A64SZ * 2),      aSrc + kn);
            CPA16(aDst + s * (A64SZ * 2) + 16, aSrc + kn + 8);
            const __half* bs = bSrc + (size_t)kn * N;
            #pragma unroll
            for (int j = 0; j < 4; j++)
                CPA16(bDst + s * (B64SZ * 2) + j * 16, bs + j * 8);
        }
        CP_COMMIT();

        uint32_t aB = aAddr + buf * (A64SZ * 2);
        uint32_t bB = bAddr + buf * (B64SZ * 2);
        #pragma unroll
        for (int kk = 0; kk < 64; kk += 16) {
            uint32_t a[2][4], b[2][4];
            ldsm4 (a[0], aB + kk * 2);
            ldsm4 (a[1], aB + kk * 2 + 16 * H64A * 2);
            ldsm4t(b[0], bB + kk * H64B * 2);
            ldsm4t(b[1], bB + kk * H64B * 2 + 16 * 2);
            #pragma unroll
            for (int mt = 0; mt < 2; mt++)
                #pragma unroll
                for (int nt = 0; nt < 4; nt++)
                    mma_f16(acc[mt][nt], a[mt],
                            b[nt >> 1][(nt & 1) * 2], b[nt >> 1][(nt & 1) * 2 + 1]);
        }
        buf++; if (buf == 3) buf = 0;
    }

    gemm_epilogue(acc, bias, R, C, Ch, N, flags, rmode, r0, c0, wr, wc, g, tg);
}

// -------------------- fp16 tensor-core attention (verified R13) -----------
#define KVSTR 72
#define KVSZ  (64 * KVSTR)

__global__ __launch_bounds__(256) void attn_h(
    const __half* __restrict__ Q, int qStride,
    const __half* __restrict__ Kp, const __half* __restrict__ Vp, int kvStride,
    __half* __restrict__ O, int Tq, int Tk, int ktiles, float scale)
{
    extern __shared__ __align__(16) char smh[];
    const int SSTh = ktiles * 64 + 8;
    __half* Ssm = (__half*)smh;
    __half* KV  = (__half*)(smh + (size_t)64 * SSTh * 2);
    float*  srow = (float*)(smh + (size_t)64 * SSTh * 2 + 2 * KVSZ * 2);

    int qt = blockIdx.x, b = blockIdx.y, h = blockIdx.z;
    int tid = threadIdx.x, warp = tid >> 5, lane = tid & 31;
    int g = lane >> 2, tg = lane & 3;
    int wm = warp >> 1, wn = warp & 1;
    int rb = wm * 16;
    int q0 = qt * 64;
    int l15 = lane & 15, lhi = lane >> 4;
    int bq = (lane & 7) + ((lane >> 3) & 1) * 8;

    const __half* Qb = Q  + (size_t)b * Tq * qStride  + h * DH;
    const __half* Kb = Kp + (size_t)b * Tk * kvStride + h * DH;
    const __half* Vb = Vp + (size_t)b * Tk * kvStride + h * DH;

    uint32_t kvBase = (uint32_t)__cvta_generic_to_shared(KV);
    uint32_t sBase  = (uint32_t)__cvta_generic_to_shared(Ssm);

    int lr = tid >> 2, lc = (tid & 3) * 16;

    {
        int rq = q0 + lr; if (rq > Tq - 1) rq = Tq - 1;
        const __half* src = Qb + (size_t)rq * qStride + lc;
        *(uint4*)&KV[lr * KVSTR + lc]     = *(const uint4*)src;
        *(uint4*)&KV[lr * KVSTR + lc + 8] = *(const uint4*)(src + 8);
    }
    __syncthreads();

    uint32_t aq[4][4];
    {
        uint32_t qA = kvBase + (uint32_t)(((rb + l15) * KVSTR + lhi * 8) * 2);
        #pragma unroll
        for (int kk = 0; kk < 4; kk++) ldsm4(aq[kk], qA + kk * 32);
    }
    __syncthreads();

    auto prefK = [&](int bf, int kt) {
        int rk = kt * 64 + lr; if (rk > Tk - 1) rk = Tk - 1;
        const __half* src = Kb + (size_t)rk * kvStride + lc;
        uint32_t dst = kvBase + (uint32_t)((bf * KVSZ + lr * KVSTR + lc) * 2);
        CPA16(dst, src);
        CPA16(dst + 16, src + 8);
        CP_COMMIT();
    };
    auto prefV = [&](int bf, int kt) {
        int rk = kt * 64 + lr; if (rk > Tk - 1) rk = Tk - 1;
        const __half* src = Vb + (size_t)rk * kvStride + lc;
        uint32_t dst = kvBase + (uint32_t)((bf * KVSZ + lr * KVSTR + lc) * 2);
        CPA16(dst, src);
        CPA16(dst + 16, src + 8);
        CP_COMMIT();
    };

    prefK(0, 0);
    for (int kt = 0; kt < ktiles; kt++) {
        if (kt + 1 < ktiles) { prefK((kt + 1) & 1, kt + 1); CP_WAIT(1); }
        else                 { CP_WAIT(0); }
        __syncthreads();

        float cS[4][4];
        #pragma unroll
        for (int nt = 0; nt < 4; nt++)
            #pragma unroll
            for (int i = 0; i < 4; i++) cS[nt][i] = 0.0f;

        uint32_t kB = kvBase + (uint32_t)(((kt & 1) * KVSZ
                     + (wn * 32 + l15) * KVSTR + lhi * 8) * 2);
        #pragma unroll
        for (int kk = 0; kk < 4; kk++) {
            uint32_t kb0[4], kb1[4];
            ldsm4(kb0, kB + kk * 32);
            ldsm4(kb1, kB + 16 * KVSTR * 2 + kk * 32);
            mma_f16(cS[0], aq[kk], kb0[0], kb0[2]);
            mma_f16(cS[1], aq[kk], kb0[1], kb0[3]);
            mma_f16(cS[2], aq[kk], kb1[0], kb1[2]);
            mma_f16(cS[3], aq[kk], kb1[1], kb1[3]);
        }

        #pragma unroll
        for (int nt = 0; nt < 4; nt++) {
            int cl = wn * 32 + nt * 8 + 2 * tg;
            int cg = kt * 64 + cl;
            float s0 = (cg     < Tk) ? cS[nt][0] * scale : -60000.0f;
            float s1 = (cg + 1 < Tk) ? cS[nt][1] * scale : -60000.0f;
            float s2 = (cg     < Tk) ? cS[nt][2] * scale : -60000.0f;
            float s3 = (cg + 1 < Tk) ? cS[nt][3] * scale : -60000.0f;
            *(__half2*)&Ssm[(rb + g) * SSTh + kt * 64 + cl]     = __floats2half2_rn(s0, s1);
            *(__half2*)&Ssm[(rb + g + 8) * SSTh + kt * 64 + cl] = __floats2half2_rn(s2, s3);
        }
        __syncthreads();
    }

    prefV(0, 0);

    {
        int row = tid >> 2, sub = tid & 3;
        __half2* Sr = (__half2*)&Ssm[row * SSTh];
        int nc2 = ktiles * 32;
        float m = -1e30f;
        for (int c = sub; c < nc2; c += 4) {
            float2 v = __half22float2(Sr[c]);
            m = fmaxf(m, fmaxf(v.x, v.y));
        }
        m = fmaxf(m, __shfl_xor_sync(0xffffffffu, m, 1));
        m = fmaxf(m, __shfl_xor_sync(0xffffffffu, m, 2));
        float s = 0.0f;
        for (int c = sub; c < nc2; c += 4) {
            float2 v = __half22float2(Sr[c]);
            float e0 = __expf(v.x - m), e1 = __expf(v.y - m);
            s += e0 + e1;
            Sr[c] = __floats2half2_rn(e0, e1);
        }
        s += __shfl_xor_sync(0xffffffffu, s, 1);
        s += __shfl_xor_sync(0xffffffffu, s, 2);
        if (sub == 0) srow[row] = 1.0f / s;
    }
    __syncthreads();

    float cO[4][4];
    #pragma unroll
    for (int nt = 0; nt < 4; nt++)
        #pragma unroll
        for (int i = 0; i < 4; i++) cO[nt][i] = 0.0f;

    uint32_t pA = sBase + (uint32_t)(((rb + l15) * SSTh + lhi * 8) * 2);
    for (int kt = 0; kt < ktiles; kt++) {
        if (kt + 1 < ktiles) { prefV((kt + 1) & 1, kt + 1); CP_WAIT(1); }
        else                 { CP_WAIT(0); }
        __syncthreads();

        uint32_t vB = kvBase + (uint32_t)(((kt & 1) * KVSZ
                     + bq * KVSTR + wn * 32 + lhi * 8) * 2);
        #pragma unroll
        for (int kk = 0; kk < 4; kk++) {
            uint32_t ap[4];
            ldsm4(ap, pA + (kt * 64 + kk * 16) * 2);
            uint32_t vb0[4], vb1[4];
            ldsm4t(vb0, vB + kk * 16 * KVSTR * 2);
            ldsm4t(vb1, vB + kk * 16 * KVSTR * 2 + 32);
            mma_f16(cO[0], ap, vb0[0], vb0[1]);
            mma_f16(cO[1], ap, vb0[2], vb0[3]);
            mma_f16(cO[2], ap, vb1[0], vb1[1]);
            mma_f16(cO[3], ap, vb1[2], vb1[3]);
        }
        __syncthreads();
    }

    float inv0 = srow[rb + g], inv1 = srow[rb + g + 8];
    #pragma unroll
    for (int nt = 0; nt < 4; nt++) {
        int dl = wn * 32 + nt * 8 + 2 * tg;
        int r0g = q0 + rb + g;
        if (r0g < Tq)
            *(__half2*)&O[((size_t)b * Tq + r0g) * DIM + h * DH + dl] =
                __floats2half2_rn(cO[nt][0] * inv0, cO[nt][1] * inv0);
        int r1g = q0 + rb + g + 8;
        if (r1g < Tq)
            *(__half2*)&O[((size_t)b * Tq + r1g) * DIM + h * DH + dl] =
                __floats2half2_rn(cO[nt][2] * inv1, cO[nt][3] * inv1);
    }
}

// -------------------- Linformer K/V projection (verified) -----------------
__global__ __launch_bounds__(256) void linproj_h(
    const __half* __restrict__ qkv, const float* __restrict__ E,
    __half* __restrict__ kproj, __half* __restrict__ vproj)
{
    __shared__ float Es[TS * 32];
    __shared__ float Ksm[TS * 64];

    int b = blockIdx.x;
    int c0 = blockIdx.y * 64;
    int zz = blockIdx.z;
    int kvsel = zz & 1;
    int kkt = zz >> 1;
    int tid = threadIdx.x;

    int colbase = DIM + kvsel * DIM + c0;
    for (int i = tid; i < TS * 64; i += 256) {
        int j = i >> 6, c = i & 63;
        Ksm[i] = __half2float(qkv[((size_t)b * TS + j) * (3 * DIM) + colbase + c]);
    }
    for (int i = tid; i < TS * 32; i += 256) {
        int j = i >> 5, q = i & 31;
        Es[i] = E[j * KL + kkt * 32 + q];
    }
    __syncthreads();

    int c = tid & 63, kg = tid >> 6;
    float acc[8];
    #pragma unroll
    for (int i = 0; i < 8; i++) acc[i] = 0.0f;

    for (int j = 0; j < TS; j++) {
        float kv = Ksm[j * 64 + c];
        #pragma unroll
        for (int i = 0; i < 8; i++)
            acc[i] += kv * Es[j * 32 + kg * 8 + i];
    }

    __half* dst = kvsel ? vproj : kproj;
    #pragma unroll
    for (int i = 0; i < 8; i++) {
        int kk = kkt * 32 + kg * 8 + i;
        dst[((size_t)b * KL + kk) * DIM + c0 + c] = __float2half_rn(acc[i]);
    }
}

// -------------------- token rearrangement (fp16-only outputs) -------------
__global__ void gather_t_kernel(const float* __restrict__ x,
                                __half* __restrict__ xth)
{
    int row = blockIdx.x;
    int p = row / TT, t = row % TT;
    const float4* s = (const float4*)(t == 0 ? x
                        : x + (size_t)(1 + (t - 1) * PATCHES + p) * DIM);
    float4 v = s[threadIdx.x];
    uint2 h = make_uint2(h2u(__floats2half2_rn(v.x, v.y)),
                         h2u(__floats2half2_rn(v.z, v.w)));
    *(uint2*)(xth + (size_t)row * DIM + threadIdx.x * 4) = h;
}

__global__ void gather_s_kernel(const float* __restrict__ yt,
                                __half* __restrict__ ysh)
{
    int row = blockIdx.x;
    int f = row / TS, t = row % TS;
    const float* src = (t == 0)
        ? yt + (size_t)((f & 63) * TT) * DIM
        : yt + (size_t)((t - 1) * TT + 1 + f) * DIM;
    float4 v = ((const float4*)src)[threadIdx.x];
    uint2 h = make_uint2(h2u(__floats2half2_rn(v.x, v.y)),
                         h2u(__floats2half2_rn(v.z, v.w)));
    *(uint2*)(ysh + (size_t)row * DIM + threadIdx.x * 4) = h;
}

// -------------------- launch ----------------------------------------------
extern "C" void kernel_launch(void* const* d_in, const int* in_sizes, int n_in,
                              void* d_out, int out_size)
{
    const float* x      = (const float*)d_in[0];
    const float* Wqkv_t = (const float*)d_in[1];
    const float* Wo_t   = (const float*)d_in[2];
    const float* Wqkv_s = (const float*)d_in[3];
    const float* Wo_s   = (const float*)d_in[4];
    const float* E      = (const float*)d_in[5];
    const float* W1     = (const float*)d_in[6];
    const float* b1     = (const float*)d_in[7];
    const float* W2     = (const float*)d_in[8];
    const float* b2     = (const float*)d_in[9];
    float* out = (float*)d_out;

    float *yt, *ys2;
    __half *xth, *ysh, *qkvh, *attnh, *ys2h, *hh, *kprojh, *vprojh;
    __half *hQt, *hOt, *hQs, *hOs, *hW1, *hW2;
    cudaGetSymbolAddress((void**)&yt,     g_yt);
    cudaGetSymbolAddress((void**)&ys2,    g_ys2);
    cudaGetSymbolAddress((void**)&xth,    g_xth);
    cudaGetSymbolAddress((void**)&ysh,    g_ysh);
    cudaGetSymbolAddress((void**)&qkvh,   g_qkvh);
    cudaGetSymbolAddress((void**)&attnh,  g_attnh);
    cudaGetSymbolAddress((void**)&ys2h,   g_ys2h);
    cudaGetSymbolAddress((void**)&hh,     g_hh);
    cudaGetSymbolAddress((void**)&kprojh, g_kprojh);
    cudaGetSymbolAddress((void**)&vprojh, g_vprojh);
    cudaGetSymbolAddress((void**)&hQt,    g_hWqkv_t);
    cudaGetSymbolAddress((void**)&hOt,    g_hWo_t);
    cudaGetSymbolAddress((void**)&hQs,    g_hWqkv_s);
    cudaGetSymbolAddress((void**)&hOs,    g_hWo_s);
    cudaGetSymbolAddress((void**)&hW1,    g_hW1);
    cudaGetSymbolAddress((void**)&hW2,    g_hW2);

    const int ktT = (TT + 63) / 64;          // 5
    const int ktS = (KL + 63) / 64;          // 2
    const int qtT = (TT + 63) / 64;          // 5
    const int qtS = (TS + 63) / 64;          // 2
    const int smemT = 64 * (ktT * 64 + 8) * 2 + 2 * KVSZ * 2 + 64 * 4;
    const int smemS = 64 * (ktS * 64 + 8) * 2 + 2 * KVSZ * 2 + 64 * 4;
    cudaFuncSetAttribute(attn_h, cudaFuncAttributeMaxDynamicSharedMemorySize, smemT);
    cudaFuncSetAttribute(gemm64, cudaFuncAttributeMaxDynamicSharedMemorySize, GSM);

    // 0) fused weight conversion
    cvt_all<<<(NCVT / 8 + 255) / 256, 256>>>(
        Wqkv_t, hQt, Wo_t, hOt, Wqkv_s, hQs, Wo_s, hOs, W1, hW1, W2, hW2);

    // 1) temporal token gather -> fp16
    gather_t_kernel<<<RT, 128>>>(x, xth);

    // 2) temporal QKV (wide N -> gemm32)
    gemm32<<<dim3(3 * DIM / 128, RT / 64), 256>>>(
        xth, hQt, nullptr, nullptr, nullptr, qkvh, RT, 3 * DIM, DIM, 0, 0);

    // 3) temporal attention
    attn_h<<<dim3(qtT, PATCHES, HEADS), 256, smemT>>>(
        qkvh, 3 * DIM, qkvh + DIM, qkvh + 2 * DIM, 3 * DIM, attnh, TT, TT, ktT, 0.125f);

    // 4) Wo_t + residual from x (narrow N -> gemm64, verified fast)
    gemm64<<<dim3(DIM / 128, RT / 64), 256, GSM>>>(
        attnh, hOt, nullptr, x, yt, nullptr, RT, DIM, DIM, FLAG_RES, 1);

    // 5) spatial gather -> fp16
    gather_s_kernel<<<RS, 128>>>(yt, ysh);

    // 6) spatial QKV (wide N -> gemm32)
    gemm32<<<dim3(3 * DIM / 128, RS / 64), 256>>>(
        ysh, hQs, nullptr, nullptr, nullptr, qkvh, RS, 3 * DIM, DIM, 0, 0);

    // 7) Linformer K/V projection
    linproj_h<<<dim3(FRAMES, DIM / 64, 8), 256>>>(qkvh, E, kprojh, vprojh);

    // 8) spatial attention (2 query tiles)
    attn_h<<<dim3(qtS, FRAMES, HEADS), 256, smemS>>>(
        qkvh, 3 * DIM, kprojh, vprojh, DIM, attnh, TS, KL, ktS, 0.125f);

    // 9) Wo_s + residual from yt (narrow N -> gemm64)
    gemm64<<<dim3(DIM / 128, RS / 64), 256, GSM>>>(
        attnh, hOs, nullptr, yt, ys2, ys2h, RS, DIM, DIM, FLAG_RES, 2);

    // 10) MLP up + bias + GELU (wide N -> gemm32)
    gemm32<<<dim3(DFF / 128, RS / 64), 256>>>(
        ys2h, hW1, b1, nullptr, nullptr, hh, RS, DFF, DIM, FLAG_BIAS | FLAG_GELU, 0);

    // 11) MLP down + bias + residual (narrow N, K=1024 -> gemm64)
    gemm64<<<dim3(DIM / 128, RS / 64), 256, GSM>>>(
        hh, hW2, b2, ys2, out, nullptr, RS, DIM, DFF, FLAG_BIAS | FLAG_RES, 0);
}

// round 17
// speedup vs baseline: 1.1727x; 1.0051x over previous
#include <cuda_runtime.h>
#include <cuda_bf16.h>
#include <cuda_fp16.h>
#include <math.h>
#include <stdint.h>

// Problem constants
#define FRAMES  256
#define PATCHES 64
#define DIM     512
#define HEADS   8
#define DH      64
#define DFF     1024
#define KL      128
#define TT      257
#define TS      65
#define RT      (PATCHES * TT)   // 16448
#define RS      (FRAMES * TS)    // 16640

#define FLAG_BIAS 1
#define FLAG_RES  2
#define FLAG_GELU 4

// -------------------- scratch --------------------------------------------
__device__ float g_yt  [RT * DIM];
__device__ float g_ys2 [RS * DIM];
// fp16 activations
__device__ __align__(16) __half g_xth  [RT * DIM];
__device__ __align__(16) __half g_ysh  [RS * DIM];
__device__ __align__(16) __half g_qkvh [RS * 3 * DIM];
__device__ __align__(16) __half g_attnh[RS * DIM];
__device__ __align__(16) __half g_ys2h [RS * DIM];
__device__ __align__(16) __half g_hh   [RS * DFF];
__device__ __align__(16) __half g_kprojh[FRAMES * KL * DIM];
__device__ __align__(16) __half g_vprojh[FRAMES * KL * DIM];
// fp16 weights
__device__ __align__(16) __half g_hWqkv_t[DIM * 3 * DIM];
__device__ __align__(16) __half g_hWo_t  [DIM * DIM];
__device__ __align__(16) __half g_hWqkv_s[DIM * 3 * DIM];
__device__ __align__(16) __half g_hWo_s  [DIM * DIM];
__device__ __align__(16) __half g_hW1    [DIM * DFF];
__device__ __align__(16) __half g_hW2    [DFF * DIM];

// -------------------- helpers --------------------------------------------
__device__ __forceinline__ void mma_f16(float (&c)[4], const uint32_t (&a)[4],
                                        uint32_t b0, uint32_t b1) {
    asm volatile(
        "mma.sync.aligned.m16n8k16.row.col.f32.f16.f16.f32 "
        "{%0,%1,%2,%3}, {%4,%5,%6,%7}, {%8,%9}, {%0,%1,%2,%3};"
        : "+f"(c[0]), "+f"(c[1]), "+f"(c[2]), "+f"(c[3])
        : "r"(a[0]), "r"(a[1]), "r"(a[2]), "r"(a[3]), "r"(b0), "r"(b1));
}

__device__ __forceinline__ void ldsm4(uint32_t (&r)[4], uint32_t addr) {
    asm volatile("ldmatrix.sync.aligned.m8n8.x4.shared.b16 {%0,%1,%2,%3}, [%4];"
        : "=r"(r[0]), "=r"(r[1]), "=r"(r[2]), "=r"(r[3]) : "r"(addr));
}
__device__ __forceinline__ void ldsm4t(uint32_t (&r)[4], uint32_t addr) {
    asm volatile("ldmatrix.sync.aligned.m8n8.x4.trans.shared.b16 {%0,%1,%2,%3}, [%4];"
        : "=r"(r[0]), "=r"(r[1]), "=r"(r[2]), "=r"(r[3]) : "r"(addr));
}

__device__ __forceinline__ uint32_t h2u(__half2 h) { return *(uint32_t*)&h; }

#define CPA16(dst, src) \
    asm volatile("cp.async.cg.shared.global [%0], [%1], 16;" :: "r"(dst), "l"(src))
#define CP_COMMIT() asm volatile("cp.async.commit_group;")
#define CP_WAIT(n)  asm volatile("cp.async.wait_group %0;" :: "n"(n))

// row permutation maps for residual reads (verified R14-R16)
__device__ __forceinline__ int map_row(int row, int mode) {
    if (mode == 1) {               // temporal residual: row -> x row
        int p = row / TT, t = row % TT;
        return (t == 0) ? 0 : 1 + (t - 1) * PATCHES + p;
    }
    if (mode == 2) {               // spatial residual: row -> yt row
        int f = row / TS, t = row % TS;
        return (t == 0) ? ((f & 63) * TT) : ((t - 1) * TT + 1 + f);
    }
    return row;
}

// -------------------- fused fp32 -> fp16 weight convert (verified) --------
#define NQW (DIM * 3 * DIM)
#define NOW (DIM * DIM)
#define NW1 (DIM * DFF)
#define NW2 (DFF * DIM)
#define NCVT (2 * NQW + 2 * NOW + NW1 + NW2)

__global__ void cvt_all(
    const float* __restrict__ w0, __half* __restrict__ h0,
    const float* __restrict__ w1, __half* __restrict__ h1,
    const float* __restrict__ w2, __half* __restrict__ h2,
    const float* __restrict__ w3, __half* __restrict__ h3,
    const float* __restrict__ w4, __half* __restrict__ h4,
    const float* __restrict__ w5, __half* __restrict__ h5)
{
    long i = ((long)blockIdx.x * 256 + threadIdx.x) * 8;
    if (i >= NCVT) return;
    const float* s; __half* d;
    if      (i < NQW)          { s = w0; d = h0; }
    else if ((i -= NQW) < NOW) { s = w1; d = h1; }
    else if ((i -= NOW) < NQW) { s = w2; d = h2; }
    else if ((i -= NQW) < NOW) { s = w3; d = h3; }
    else if ((i -= NOW) < NW1) { s = w4; d = h4; }
    else    { i -= NW1;          s = w5; d = h5; }
    float4 a = *(const float4*)(s + i), b = *(const float4*)(s + i + 4);
    uint4 u = make_uint4(
        h2u(__floats2half2_rn(a.x, a.y)), h2u(__floats2half2_rn(a.z, a.w)),
        h2u(__floats2half2_rn(b.x, b.y)), h2u(__floats2half2_rn(b.z, b.w)));
    *(uint4*)(d + i) = u;
}

// -------------------- gemm128: 128x128x32 tile, cp.async, ldmatrix --------
#define HA 40     // A stage row stride (halves): 80B = 5x16B (odd)
#define HB 136    // B stage row stride (halves): 272B = 17x16B (odd)
#define A128SZ (128 * HA)   // 5120 halves / 10240 B per stage
#define B128SZ (32 * HB)    // 4352 halves /  8704 B per stage
#define STG 3
#define GSM128 ((A128SZ + B128SZ) * STG * 2)   // 56832 bytes

__global__ __launch_bounds__(256) void gemm128(
    const __half* __restrict__ A, const __half* __restrict__ B,
    const float* __restrict__ bias, const float* __restrict__ R,
    float* __restrict__ C, __half* __restrict__ Ch,
    int M, int N, int K, int flags, int rmode)
{
    extern __shared__ __align__(16) __half sh[];
    __half* As = sh;
    __half* Bs = sh + STG * A128SZ;

    int tid = threadIdx.x;
    int warp = tid >> 5, lane = tid & 31;
    int wr = warp & 1;             // 2 x 64-row halves
    int wc = warp >> 1;            // 4 x 32-col groups
    int r0 = blockIdx.y * 128;
    int c0 = blockIdx.x * 128;
    int g = lane >> 2, tg = lane & 3;

    float acc[4][4][4];
    #pragma unroll
    for (int mt = 0; mt < 4; mt++)
        #pragma unroll
        for (int nt = 0; nt < 4; nt++)
            #pragma unroll
            for (int i = 0; i < 4; i++) acc[mt][nt][i] = 0.0f;

    // staging: A 128 rows x 32 cols (2 threads/row, 16 cols each);
    //          B 32 rows x 128 cols (8 threads/row, 16 cols each)
    int ar = tid >> 1, ac = (tid & 1) * 16;
    int arow = r0 + ar; if (arow > M - 1) arow = M - 1;     // clamp OOB rows
    const __half* aSrc = A + (size_t)arow * K + ac;
    int br_ = tid >> 3, bc_ = (tid & 7) * 16;
    const __half* bSrc = B + (size_t)br_ * N + c0 + bc_;
    uint32_t aDst = (uint32_t)__cvta_generic_to_shared(&As[ar * HA + ac]);
    uint32_t bDst = (uint32_t)__cvta_generic_to_shared(&Bs[br_ * HB + bc_]);

    #pragma unroll
    for (int s = 0; s < STG - 1; s++) {
        int k0 = s * 32;
        CPA16(aDst + s * (A128SZ * 2),      aSrc + k0);
        CPA16(aDst + s * (A128SZ * 2) + 16, aSrc + k0 + 8);
        const __half* bs = bSrc + (size_t)k0 * N;
        CPA16(bDst + s * (B128SZ * 2),      bs);
        CPA16(bDst + s * (B128SZ * 2) + 16, bs + 8);
        CP_COMMIT();
    }

    int l15 = lane & 15, lhi = lane >> 4;
    uint32_t aAddr = (uint32_t)__cvta_generic_to_shared(As)
                   + (uint32_t)(((wr * 64 + l15) * HA + lhi * 8) * 2);
    int bq = (lane & 7) + ((lane >> 3) & 1) * 8;
    uint32_t bAddr = (uint32_t)__cvta_generic_to_shared(Bs)
                   + (uint32_t)((bq * HB + wc * 32 + lhi * 8) * 2);

    int buf = 0;
    for (int k0 = 0; k0 < K; k0 += 32) {
        CP_WAIT(STG - 2);
        __syncthreads();

        int kn = k0 + (STG - 1) * 32;
        if (kn < K) {
            int s = buf + (STG - 1); if (s >= STG) s -= STG;
            CPA16(aDst + s * (A128SZ * 2),      aSrc + kn);
            CPA16(aDst + s * (A128SZ * 2) + 16, aSrc + kn + 8);
            const __half* bs = bSrc + (size_t)kn * N;
            CPA16(bDst + s * (B128SZ * 2),      bs);
            CPA16(bDst + s * (B128SZ * 2) + 16, bs + 8);
        }
        CP_COMMIT();

        uint32_t aB = aAddr + buf * (A128SZ * 2);
        uint32_t bB = bAddr + buf * (B128SZ * 2);
        #pragma unroll
        for (int kk = 0; kk < 32; kk += 16) {
            uint32_t a[4][4], b[2][4];
            #pragma unroll
            for (int mt = 0; mt < 4; mt++)
                ldsm4(a[mt], aB + mt * 16 * HA * 2 + kk * 2);
            ldsm4t(b[0], bB + kk * HB * 2);
            ldsm4t(b[1], bB + kk * HB * 2 + 16 * 2);
            #pragma unroll
            for (int mt = 0; mt < 4; mt++)
                #pragma unroll
                for (int nt = 0; nt < 4; nt++)
                    mma_f16(acc[mt][nt], a[mt],
                            b[nt >> 1][(nt & 1) * 2], b[nt >> 1][(nt & 1) * 2 + 1]);
        }
        buf++; if (buf == STG) buf = 0;
    }

    // epilogue (row-guarded for M % 128 != 0)
    #pragma unroll
    for (int mt = 0; mt < 4; mt++) {
        #pragma unroll
        for (int nt = 0; nt < 4; nt++) {
            int col = c0 + wc * 32 + nt * 8 + 2 * tg;
            #pragma unroll
            for (int half = 0; half < 2; half++) {
                int row = r0 + wr * 64 + mt * 16 + g + half * 8;
                if (row >= M) continue;
                float v0 = acc[mt][nt][half * 2 + 0];
                float v1 = acc[mt][nt][half * 2 + 1];
                if (flags & FLAG_BIAS) { v0 += bias[col]; v1 += bias[col + 1]; }
                if (flags & FLAG_GELU) {
                    v0 = 0.5f * v0 * (1.0f + erff(v0 * 0.70710678118654752f));
                    v1 = 0.5f * v1 * (1.0f + erff(v1 * 0.70710678118654752f));
                }
                if (flags & FLAG_RES) {
                    int rrow = map_row(row, rmode);
                    float2 rr = *(const float2*)&R[(size_t)rrow * N + col];
                    v0 += rr.x; v1 += rr.y;
                }
                if (C)
                    *(float2*)&C[(size_t)row * N + col] = make_float2(v0, v1);
                if (Ch)
                    *(__half2*)&Ch[(size_t)row * N + col] = __floats2half2_rn(v0, v1);
            }
        }
    }
}

// -------------------- fp16 tensor-core attention (verified R13) -----------
#define KVSTR 72
#define KVSZ  (64 * KVSTR)

__global__ __launch_bounds__(256) void attn_h(
    const __half* __restrict__ Q, int qStride,
    const __half* __restrict__ Kp, const __half* __restrict__ Vp, int kvStride,
    __half* __restrict__ O, int Tq, int Tk, int ktiles, float scale)
{
    extern __shared__ __align__(16) char smh[];
    const int SSTh = ktiles * 64 + 8;
    __half* Ssm = (__half*)smh;
    __half* KV  = (__half*)(smh + (size_t)64 * SSTh * 2);
    float*  srow = (float*)(smh + (size_t)64 * SSTh * 2 + 2 * KVSZ * 2);

    int qt = blockIdx.x, b = blockIdx.y, h = blockIdx.z;
    int tid = threadIdx.x, warp = tid >> 5, lane = tid & 31;
    int g = lane >> 2, tg = lane & 3;
    int wm = warp >> 1, wn = warp & 1;
    int rb = wm * 16;
    int q0 = qt * 64;
    int l15 = lane & 15, lhi = lane >> 4;
    int bq = (lane & 7) + ((lane >> 3) & 1) * 8;

    const __half* Qb = Q  + (size_t)b * Tq * qStride  + h * DH;
    const __half* Kb = Kp + (size_t)b * Tk * kvStride + h * DH;
    const __half* Vb = Vp + (size_t)b * Tk * kvStride + h * DH;

    uint32_t kvBase = (uint32_t)__cvta_generic_to_shared(KV);
    uint32_t sBase  = (uint32_t)__cvta_generic_to_shared(Ssm);

    int lr = tid >> 2, lc = (tid & 3) * 16;

    {
        int rq = q0 + lr; if (rq > Tq - 1) rq = Tq - 1;
        const __half* src = Qb + (size_t)rq * qStride + lc;
        *(uint4*)&KV[lr * KVSTR + lc]     = *(const uint4*)src;
        *(uint4*)&KV[lr * KVSTR + lc + 8] = *(const uint4*)(src + 8);
    }
    __syncthreads();

    uint32_t aq[4][4];
    {
        uint32_t qA = kvBase + (uint32_t)(((rb + l15) * KVSTR + lhi * 8) * 2);
        #pragma unroll
        for (int kk = 0; kk < 4; kk++) ldsm4(aq[kk], qA + kk * 32);
    }
    __syncthreads();

    auto prefK = [&](int bf, int kt) {
        int rk = kt * 64 + lr; if (rk > Tk - 1) rk = Tk - 1;
        const __half* src = Kb + (size_t)rk * kvStride + lc;
        uint32_t dst = kvBase + (uint32_t)((bf * KVSZ + lr * KVSTR + lc) * 2);
        CPA16(dst, src);
        CPA16(dst + 16, src + 8);
        CP_COMMIT();
    };
    auto prefV = [&](int bf, int kt) {
        int rk = kt * 64 + lr; if (rk > Tk - 1) rk = Tk - 1;
        const __half* src = Vb + (size_t)rk * kvStride + lc;
        uint32_t dst = kvBase + (uint32_t)((bf * KVSZ + lr * KVSTR + lc) * 2);
        CPA16(dst, src);
        CPA16(dst + 16, src + 8);
        CP_COMMIT();
    };

    prefK(0, 0);
    for (int kt = 0; kt < ktiles; kt++) {
        if (kt + 1 < ktiles) { prefK((kt + 1) & 1, kt + 1); CP_WAIT(1); }
        else                 { CP_WAIT(0); }
        __syncthreads();

        float cS[4][4];
        #pragma unroll
        for (int nt = 0; nt < 4; nt++)
            #pragma unroll
            for (int i = 0; i < 4; i++) cS[nt][i] = 0.0f;

        uint32_t kB = kvBase + (uint32_t)(((kt & 1) * KVSZ
                     + (wn * 32 + l15) * KVSTR + lhi * 8) * 2);
        #pragma unroll
        for (int kk = 0; kk < 4; kk++) {
            uint32_t kb0[4], kb1[4];
            ldsm4(kb0, kB + kk * 32);
            ldsm4(kb1, kB + 16 * KVSTR * 2 + kk * 32);
            mma_f16(cS[0], aq[kk], kb0[0], kb0[2]);
            mma_f16(cS[1], aq[kk], kb0[1], kb0[3]);
            mma_f16(cS[2], aq[kk], kb1[0], kb1[2]);
            mma_f16(cS[3], aq[kk], kb1[1], kb1[3]);
        }

        #pragma unroll
        for (int nt = 0; nt < 4; nt++) {
            int cl = wn * 32 + nt * 8 + 2 * tg;
            int cg = kt * 64 + cl;
            float s0 = (cg     < Tk) ? cS[nt][0] * scale : -60000.0f;
            float s1 = (cg + 1 < Tk) ? cS[nt][1] * scale : -60000.0f;
            float s2 = (cg     < Tk) ? cS[nt][2] * scale : -60000.0f;
            float s3 = (cg + 1 < Tk) ? cS[nt][3] * scale : -60000.0f;
            *(__half2*)&Ssm[(rb + g) * SSTh + kt * 64 + cl]     = __floats2half2_rn(s0, s1);
            *(__half2*)&Ssm[(rb + g + 8) * SSTh + kt * 64 + cl] = __floats2half2_rn(s2, s3);
        }
        __syncthreads();
    }

    prefV(0, 0);

    {
        int row = tid >> 2, sub = tid & 3;
        __half2* Sr = (__half2*)&Ssm[row * SSTh];
        int nc2 = ktiles * 32;
        float m = -1e30f;
        for (int c = sub; c < nc2; c += 4) {
            float2 v = __half22float2(Sr[c]);
            m = fmaxf(m, fmaxf(v.x, v.y));
        }
        m = fmaxf(m, __shfl_xor_sync(0xffffffffu, m, 1));
        m = fmaxf(m, __shfl_xor_sync(0xffffffffu, m, 2));
        float s = 0.0f;
        for (int c = sub; c < nc2; c += 4) {
            float2 v = __half22float2(Sr[c]);
            float e0 = __expf(v.x - m), e1 = __expf(v.y - m);
            s += e0 + e1;
            Sr[c] = __floats2half2_rn(e0, e1);
        }
        s += __shfl_xor_sync(0xffffffffu, s, 1);
        s += __shfl_xor_sync(0xffffffffu, s, 2);
        if (sub == 0) srow[row] = 1.0f / s;
    }
    __syncthreads();

    float cO[4][4];
    #pragma unroll
    for (int nt = 0; nt < 4; nt++)
        #pragma unroll
        for (int i = 0; i < 4; i++) cO[nt][i] = 0.0f;

    uint32_t pA = sBase + (uint32_t)(((rb + l15) * SSTh + lhi * 8) * 2);
    for (int kt = 0; kt < ktiles; kt++) {
        if (kt + 1 < ktiles) { prefV((kt + 1) & 1, kt + 1); CP_WAIT(1); }
        else                 { CP_WAIT(0); }
        __syncthreads();

        uint32_t vB = kvBase + (uint32_t)(((kt & 1) * KVSZ
                     + bq * KVSTR + wn * 32 + lhi * 8) * 2);
        #pragma unroll
        for (int kk = 0; kk < 4; kk++) {
            uint32_t ap[4];
            ldsm4(ap, pA + (kt * 64 + kk * 16) * 2);
            uint32_t vb0[4], vb1[4];
            ldsm4t(vb0, vB + kk * 16 * KVSTR * 2);
            ldsm4t(vb1, vB + kk * 16 * KVSTR * 2 + 32);
            mma_f16(cO[0], ap, vb0[0], vb0[1]);
            mma_f16(cO[1], ap, vb0[2], vb0[3]);
            mma_f16(cO[2], ap, vb1[0], vb1[1]);
            mma_f16(cO[3], ap, vb1[2], vb1[3]);
        }
        __syncthreads();
    }

    float inv0 = srow[rb + g], inv1 = srow[rb + g + 8];
    #pragma unroll
    for (int nt = 0; nt < 4; nt++) {
        int dl = wn * 32 + nt * 8 + 2 * tg;
        int r0g = q0 + rb + g;
        if (r0g < Tq)
            *(__half2*)&O[((size_t)b * Tq + r0g) * DIM + h * DH + dl] =
                __floats2half2_rn(cO[nt][0] * inv0, cO[nt][1] * inv0);
        int r1g = q0 + rb + g + 8;
        if (r1g < Tq)
            *(__half2*)&O[((size_t)b * Tq + r1g) * DIM + h * DH + dl] =
                __floats2half2_rn(cO[nt][2] * inv1, cO[nt][3] * inv1);
    }
}

// -------------------- Linformer K/V projection (verified) -----------------
__global__ __launch_bounds__(256) void linproj_h(
    const __half* __restrict__ qkv, const float* __restrict__ E,
    __half* __restrict__ kproj, __half* __restrict__ vproj)
{
    __shared__ float Es[TS * 32];
    __shared__ float Ksm[TS * 64];

    int b = blockIdx.x;
    int c0 = blockIdx.y * 64;
    int zz = blockIdx.z;
    int kvsel = zz & 1;
    int kkt = zz >> 1;
    int tid = threadIdx.x;

    int colbase = DIM + kvsel * DIM + c0;
    for (int i = tid; i < TS * 64; i += 256) {
        int j = i >> 6, c = i & 63;
        Ksm[i] = __half2float(qkv[((size_t)b * TS + j) * (3 * DIM) + colbase + c]);
    }
    for (int i = tid; i < TS * 32; i += 256) {
        int j = i >> 5, q = i & 31;
        Es[i] = E[j * KL + kkt * 32 + q];
    }
    __syncthreads();

    int c = tid & 63, kg = tid >> 6;
    float acc[8];
    #pragma unroll
    for (int i = 0; i < 8; i++) acc[i] = 0.0f;

    for (int j = 0; j < TS; j++) {
        float kv = Ksm[j * 64 + c];
        #pragma unroll
        for (int i = 0; i < 8; i++)
            acc[i] += kv * Es[j * 32 + kg * 8 + i];
    }

    __half* dst = kvsel ? vproj : kproj;
    #pragma unroll
    for (int i = 0; i < 8; i++) {
        int kk = kkt * 32 + kg * 8 + i;
        dst[((size_t)b * KL + kk) * DIM + c0 + c] = __float2half_rn(acc[i]);
    }
}

// -------------------- token rearrangement (fp16-only outputs) -------------
__global__ void gather_t_kernel(const float* __restrict__ x,
                                __half* __restrict__ xth)
{
    int row = blockIdx.x;
    int p = row / TT, t = row % TT;
    const float4* s = (const float4*)(t == 0 ? x
                        : x + (size_t)(1 + (t - 1) * PATCHES + p) * DIM);
    float4 v = s[threadIdx.x];
    uint2 h = make_uint2(h2u(__floats2half2_rn(v.x, v.y)),
                         h2u(__floats2half2_rn(v.z, v.w)));
    *(uint2*)(xth + (size_t)row * DIM + threadIdx.x * 4) = h;
}

__global__ void gather_s_kernel(const float* __restrict__ yt,
                                __half* __restrict__ ysh)
{
    int row = blockIdx.x;
    int f = row / TS, t = row % TS;
    const float* src = (t == 0)
        ? yt + (size_t)((f & 63) * TT) * DIM
        : yt + (size_t)((t - 1) * TT + 1 + f) * DIM;
    float4 v = ((const float4*)src)[threadIdx.x];
    uint2 h = make_uint2(h2u(__floats2half2_rn(v.x, v.y)),
                         h2u(__floats2half2_rn(v.z, v.w)));
    *(uint2*)(ysh + (size_t)row * DIM + threadIdx.x * 4) = h;
}

// -------------------- launch ----------------------------------------------
extern "C" void kernel_launch(void* const* d_in, const int* in_sizes, int n_in,
                              void* d_out, int out_size)
{
    const float* x      = (const float*)d_in[0];
    const float* Wqkv_t = (const float*)d_in[1];
    const float* Wo_t   = (const float*)d_in[2];
    const float* Wqkv_s = (const float*)d_in[3];
    const float* Wo_s   = (const float*)d_in[4];
    const float* E      = (const float*)d_in[5];
    const float* W1     = (const float*)d_in[6];
    const float* b1     = (const float*)d_in[7];
    const float* W2     = (const float*)d_in[8];
    const float* b2     = (const float*)d_in[9];
    float* out = (float*)d_out;

    float *yt, *ys2;
    __half *xth, *ysh, *qkvh, *attnh, *ys2h, *hh, *kprojh, *vprojh;
    __half *hQt, *hOt, *hQs, *hOs, *hW1, *hW2;
    cudaGetSymbolAddress((void**)&yt,     g_yt);
    cudaGetSymbolAddress((void**)&ys2,    g_ys2);
    cudaGetSymbolAddress((void**)&xth,    g_xth);
    cudaGetSymbolAddress((void**)&ysh,    g_ysh);
    cudaGetSymbolAddress((void**)&qkvh,   g_qkvh);
    cudaGetSymbolAddress((void**)&attnh,  g_attnh);
    cudaGetSymbolAddress((void**)&ys2h,   g_ys2h);
    cudaGetSymbolAddress((void**)&hh,     g_hh);
    cudaGetSymbolAddress((void**)&kprojh, g_kprojh);
    cudaGetSymbolAddress((void**)&vprojh, g_vprojh);
    cudaGetSymbolAddress((void**)&hQt,    g_hWqkv_t);
    cudaGetSymbolAddress((void**)&hOt,    g_hWo_t);
    cudaGetSymbolAddress((void**)&hQs,    g_hWqkv_s);
    cudaGetSymbolAddress((void**)&hOs,    g_hWo_s);
    cudaGetSymbolAddress((void**)&hW1,    g_hW1);
    cudaGetSymbolAddress((void**)&hW2,    g_hW2);

    const int ktT = (TT + 63) / 64;          // 5
    const int ktS = (KL + 63) / 64;          // 2
    const int qtT = (TT + 63) / 64;          // 5
    const int qtS = (TS + 63) / 64;          // 2
    const int smemT = 64 * (ktT * 64 + 8) * 2 + 2 * KVSZ * 2 + 64 * 4;
    const int smemS = 64 * (ktS * 64 + 8) * 2 + 2 * KVSZ * 2 + 64 * 4;
    const int mtT = (RT + 127) / 128;        // 129 (last tile partial)
    const int mtS = (RS + 127) / 128;        // 130 (exact)
    cudaFuncSetAttribute(attn_h, cudaFuncAttributeMaxDynamicSharedMemorySize, smemT);
    cudaFuncSetAttribute(gemm128, cudaFuncAttributeMaxDynamicSharedMemorySize, GSM128);

    // 0) fused weight conversion
    cvt_all<<<(NCVT / 8 + 255) / 256, 256>>>(
        Wqkv_t, hQt, Wo_t, hOt, Wqkv_s, hQs, Wo_s, hOs, W1, hW1, W2, hW2);

    // 1) temporal token gather -> fp16
    gather_t_kernel<<<RT, 128>>>(x, xth);

    // 2) temporal QKV
    gemm128<<<dim3(3 * DIM / 128, mtT), 256, GSM128>>>(
        xth, hQt, nullptr, nullptr, nullptr, qkvh, RT, 3 * DIM, DIM, 0, 0);

    // 3) temporal attention
    attn_h<<<dim3(qtT, PATCHES, HEADS), 256, smemT>>>(
        qkvh, 3 * DIM, qkvh + DIM, qkvh + 2 * DIM, 3 * DIM, attnh, TT, TT, ktT, 0.125f);

    // 4) Wo_t + residual from x (rmode=1) -> yt fp32
    gemm128<<<dim3(DIM / 128, mtT), 256, GSM128>>>(
        attnh, hOt, nullptr, x, yt, nullptr, RT, DIM, DIM, FLAG_RES, 1);

    // 5) spatial gather -> fp16
    gather_s_kernel<<<RS, 128>>>(yt, ysh);

    // 6) spatial QKV
    gemm128<<<dim3(3 * DIM / 128, mtS), 256, GSM128>>>(
        ysh, hQs, nullptr, nullptr, nullptr, qkvh, RS, 3 * DIM, DIM, 0, 0);

    // 7) Linformer K/V projection
    linproj_h<<<dim3(FRAMES, DIM / 64, 8), 256>>>(qkvh, E, kprojh, vprojh);

    // 8) spatial attention (2 query tiles)
    attn_h<<<dim3(qtS, FRAMES, HEADS), 256, smemS>>>(
        qkvh, 3 * DIM, kprojh, vprojh, DIM, attnh, TS, KL, ktS, 0.125f);

    // 9) Wo_s + residual from yt (rmode=2) -> ys2 fp32 + ys2h fp16
    gemm128<<<dim3(DIM / 128, mtS), 256, GSM128>>>(
        attnh, hOs, nullptr, yt, ys2, ys2h, RS, DIM, DIM, FLAG_RES, 2);

    // 10) MLP up + bias + GELU (fp16 output)
    gemm128<<<dim3(DFF / 128, mtS), 256, GSM128>>>(
        ys2h, hW1, b1, nullptr, nullptr, hh, RS, DFF, DIM, FLAG_BIAS | FLAG_GELU, 0);

    // 11) MLP down + bias + residual -> final fp32 output
    gemm128<<<dim3(DIM / 128, mtS), 256, GSM128>>>(
        hh, hW2, b2, ys2, out, nullptr, RS, DIM, DFF, FLAG_BIAS | FLAG_RES, 0);
}